// round 16
// baseline (speedup 1.0000x reference)
#include <cuda_runtime.h>
#include <cuda_fp16.h>

#define N_NODES 50000
#define N_EDGES 800000
#define DD 128
#define NEG 0.2f
#define NLAB 8
#define ET (N_EDGES + N_NODES)
#define WSZ (7 * DD * DD)
#define NB_SCAN 49   // ceil(50000/1024)
#define XP 136       // padded smem row stride (halfs): conflict-free
#define OX_SMEM (2 * 128 * XP * 2)   // xs(128*XP) + ws(128*XP) halfs = 69632 B

// ---------------- device scratch (no allocs allowed) ----------------
__device__ __align__(16) uint2 g_oxh[N_NODES * 32];  // fp16x4 packed transformed features
__device__ __align__(16) __half g_Wh[WSZ];           // fp16 weights (pre-converted)
__device__ float g_ai[N_NODES];
__device__ float g_aj[N_NODES];
__device__ unsigned g_ajmax_u;                       // ordered-uint encoded max(aj)
__device__ int   g_order[N_NODES];
__device__ int   g_counts[NLAB];
__device__ int   g_base[NLAB + 1];
__device__ int   g_lcur[NLAB];                       // relative label cursors (start 0)
__device__ int   g_deg[N_NODES];
__device__ int   g_off[N_NODES + 1];
__device__ int   g_cur[N_NODES];
__device__ int   g_csr[ET];
__device__ int   g_part[NB_SCAN];

__device__ __forceinline__ unsigned fenc(float f) {
    unsigned u = __float_as_uint(f);
    return (u & 0x80000000u) ? ~u : (u | 0x80000000u);
}
__device__ __forceinline__ float fdec(unsigned u) {
    return (u & 0x80000000u) ? __uint_as_float(u ^ 0x80000000u)
                             : __uint_as_float(~u);
}
__device__ __forceinline__ float lrelu(float a) { return a > 0.f ? a : NEG * a; }

// ---------------- init: counters, degrees, W->fp16 ----------------
__global__ void k_init(const float* __restrict__ W) {
    int i = blockIdx.x * blockDim.x + threadIdx.x;
    if (i < NLAB) { g_counts[i] = 0; g_lcur[i] = 0; }
    if (i == NLAB) g_ajmax_u = 0u;   // encodes -inf
    if (i < N_NODES) g_deg[i] = 1;   // self loop pre-counted
    if (i < WSZ) g_Wh[i] = __float2half_rn(W[i]);
}

// ======== stream B: label chain ========

// label histogram (warp-aggregated)
__global__ void k_lab(const int* __restrict__ label) {
    int i = blockIdx.x * blockDim.x + threadIdx.x;
    if (i >= N_NODES) return;
    int lb = label[i];
    if (lb < 1 || lb > 7) lb = 0;
    unsigned act = __activemask();
    unsigned peers = __match_any_sync(act, lb);
    int leader = __ffs(peers) - 1;
    if ((int)(threadIdx.x & 31) == leader)
        atomicAdd(&g_counts[lb], __popc(peers));
}

// label bases + label-group scatter of node ids into g_order
__global__ void k_scat(const int* __restrict__ label) {
    __shared__ int sbase[NLAB];
    int t = threadIdx.x;
    int i = blockIdx.x * blockDim.x + t;
    if (t == 0) {
        int bb = 0;
        for (int k = 0; k < NLAB; k++) {
            sbase[k] = bb;
            if (blockIdx.x == 0) g_base[k] = bb;
            bb += g_counts[k];
        }
        if (blockIdx.x == 0) g_base[NLAB] = bb;
    }
    __syncthreads();
    if (i >= N_NODES) return;
    int lb = label[i];
    if (lb < 1 || lb > 7) lb = 0;
    int lane = t & 31;
    unsigned act = __activemask();
    unsigned peers = __match_any_sync(act, lb);
    int leader = __ffs(peers) - 1;
    int rank = __popc(peers & ((1u << lane) - 1u));
    int rel = 0;
    if (lane == leader) rel = atomicAdd(&g_lcur[lb], __popc(peers));
    rel = __shfl_sync(act, rel, leader);
    g_order[sbase[lb] + rel + rank] = i;
}

// tensor-core label-grouped GEMM, 128-node tile, 256 threads / 8 warps.
// Warp w computes rows [16w, 16w+16) x full N=128 (R7-proven fragment map).
// fp16 W staged ONCE per block; coalesced STG.64 ox flush (R15-proven).
__global__ void __launch_bounds__(256) k_ox(const float* __restrict__ x,
                                            const float* __restrict__ att) {
    int k = blockIdx.y;
    int gbase = g_base[k];
    int start = gbase + blockIdx.x * 128;
    int end   = gbase + g_counts[k];
    if (start >= end) return;
    int nEff = min(128, end - start);

    extern __shared__ __align__(16) __half dsm[];
    __half* xs = dsm;                  // 128 x XP
    __half* ws = dsm + 128 * XP;       // 128 x XP (W during mma; ox staging after)
    __shared__ float att_s[2 * DD];
    __shared__ int nid[128];
    __shared__ unsigned s_ajmax;

    int tid = threadIdx.x;
    int lane = tid & 31, wid = tid >> 5;
    if (tid < 128) nid[tid] = (tid < nEff) ? g_order[start + tid] : g_order[start];
    if (tid < 2 * DD) att_s[tid] = att[tid];
    if (tid == 0) s_ajmax = 0u;
    __syncthreads();

    // stage x rows (fp32 -> fp16, half-row per thread) + W tile (fp16, int4)
    {
        int j = tid >> 1, part = tid & 1;
        const float4* xr = (const float4*)x + (size_t)nid[j] * 32 + part * 16;
        __half2* dst = (__half2*)(xs + j * XP + part * 64);
#pragma unroll
        for (int i = 0; i < 16; i++) {
            float4 v = xr[i];
            dst[i * 2 + 0] = __floats2half2_rn(v.x, v.y);
            dst[i * 2 + 1] = __floats2half2_rn(v.z, v.w);
        }
    }
    if (k > 0) {
        const int4* wsrc = (const int4*)(g_Wh + (size_t)(k - 1) * DD * DD);
#pragma unroll
        for (int it = 0; it < 8; it++) {
            int idx2 = tid + it * 256;       // 0..2047
            int dr = idx2 >> 4, ii = idx2 & 15;
            *(int4*)(ws + dr * XP + ii * 8) = wsrc[idx2];
        }
    }
    __syncthreads();   // xs + ws + att_s visible (single barrier, incl. k==0 path)

    float d[16][4];
#pragma unroll
    for (int nt = 0; nt < 16; nt++) { d[nt][0] = d[nt][1] = d[nt][2] = d[nt][3] = 0.f; }

    int wrow0 = wid * 16;

    if (k > 0) {
#pragma unroll
        for (int kt = 0; kt < 8; kt++) {
            int kb = kt * 16;
            unsigned a0, a1, a2, a3;
            {
                int r  = (lane & 7) + ((lane >> 3) & 1) * 8;
                int cc = (lane >> 4) * 8;
                const __half* ap = xs + (wrow0 + r) * XP + (kb + cc);
                unsigned sa = (unsigned)__cvta_generic_to_shared(ap);
                asm volatile("ldmatrix.sync.aligned.m8n8.x4.shared.b16 {%0,%1,%2,%3}, [%4];"
                             : "=r"(a0), "=r"(a1), "=r"(a2), "=r"(a3) : "r"(sa));
            }
#pragma unroll
            for (int np = 0; np < 8; np++) {
                int n0 = np * 16;
                unsigned b0, b1, b2, b3;
                {
                    int kr = kb + (lane & 7) + ((lane >> 3) & 1) * 8;
                    int nc = n0 + (lane >> 4) * 8;
                    const __half* bp = ws + kr * XP + nc;
                    unsigned sb = (unsigned)__cvta_generic_to_shared(bp);
                    asm volatile("ldmatrix.sync.aligned.m8n8.x4.trans.shared.b16 {%0,%1,%2,%3}, [%4];"
                                 : "=r"(b0), "=r"(b1), "=r"(b2), "=r"(b3) : "r"(sb));
                }
                asm volatile("mma.sync.aligned.m16n8k16.row.col.f32.f16.f16.f32 "
                             "{%0,%1,%2,%3}, {%4,%5,%6,%7}, {%8,%9}, {%0,%1,%2,%3};"
                             : "+f"(d[np*2][0]), "+f"(d[np*2][1]), "+f"(d[np*2][2]), "+f"(d[np*2][3])
                             : "r"(a0), "r"(a1), "r"(a2), "r"(a3), "r"(b0), "r"(b1));
                asm volatile("mma.sync.aligned.m16n8k16.row.col.f32.f16.f16.f32 "
                             "{%0,%1,%2,%3}, {%4,%5,%6,%7}, {%8,%9}, {%0,%1,%2,%3};"
                             : "+f"(d[np*2+1][0]), "+f"(d[np*2+1][1]), "+f"(d[np*2+1][2]), "+f"(d[np*2+1][3])
                             : "r"(a0), "r"(a1), "r"(a2), "r"(a3), "r"(b2), "r"(b3));
            }
        }
    }
    __syncthreads();   // all warps done reading ws -> reuse as ox staging

    __half* os = ws;   // 128 x XP ox staging

    // fragment-native dots + conflict-free smem ox store (R7 mapping, warp-local rows)
    int q  = lane & 3;
    int r0 = wrow0 + (lane >> 2);
    int r1 = r0 + 8;
    int j0ok = (r0 < nEff), j1ok = (r1 < nEff);
    int node0 = nid[r0], node1 = nid[r1];

    float si0 = 0.f, sj0 = 0.f, si1 = 0.f, sj1 = 0.f;
#pragma unroll
    for (int nt = 0; nt < 16; nt++) {
        int cc = nt * 8 + 2 * q;
        float av0 = att_s[cc], av1 = att_s[cc + 1];
        float bv0 = att_s[DD + cc], bv1 = att_s[DD + cc + 1];
        float2 x0 = __half22float2(*(const __half2*)(xs + r0 * XP + cc));
        float2 x1 = __half22float2(*(const __half2*)(xs + r1 * XP + cc));
        float v00 = x0.x + d[nt][0], v01 = x0.y + d[nt][1];
        float v10 = x1.x + d[nt][2], v11 = x1.y + d[nt][3];
        si0 += v00 * av0 + v01 * av1;
        sj0 += v00 * bv0 + v01 * bv1;
        si1 += v10 * av0 + v11 * av1;
        sj1 += v10 * bv0 + v11 * bv1;
        *(__half2*)(os + r0 * XP + cc) = __floats2half2_rn(v00, v01);
        *(__half2*)(os + r1 * XP + cc) = __floats2half2_rn(v10, v11);
    }
#pragma unroll
    for (int o = 1; o <= 2; o <<= 1) {
        si0 += __shfl_xor_sync(0xFFFFFFFFu, si0, o);
        sj0 += __shfl_xor_sync(0xFFFFFFFFu, sj0, o);
        si1 += __shfl_xor_sync(0xFFFFFFFFu, si1, o);
        sj1 += __shfl_xor_sync(0xFFFFFFFFu, sj1, o);
    }
    if (q == 0) {
        unsigned mx = 0u;
        if (j0ok) { g_ai[node0] = si0; g_aj[node0] = sj0; mx = fenc(sj0); }
        if (j1ok) { g_ai[node1] = si1; g_aj[node1] = sj1; unsigned m1 = fenc(sj1); if (m1 > mx) mx = m1; }
        if (mx) atomicMax(&s_ajmax, mx);
    }

    // coalesced ox flush: warp flushes its OWN 16 rows (os rows wid*16..+15
    // were written only by this warp) -> STG.64, one contiguous 256B row each
    {
#pragma unroll
        for (int rr = 0; rr < 16; rr++) {
            int j = wrow0 + rr;
            if (j < nEff) {
                uint2 v = *(const uint2*)(os + j * XP + lane * 4);
                g_oxh[(size_t)nid[j] * 32 + lane] = v;
            }
        }
    }
    __syncthreads();
    if (tid == 0 && s_ajmax) atomicMax(&g_ajmax_u, s_ajmax);
}

// ======== stream A (default): degree chain ========

// in-degree count, 2 edges/thread
__global__ void k_deg(const int* __restrict__ ei) {
    int i = blockIdx.x * blockDim.x + threadIdx.x;
    int e2 = i * 2;
    if (e2 < N_EDGES) {
        int2 d2 = *(const int2*)(ei + N_EDGES + e2);
        atomicAdd(&g_deg[d2.x], 1);
        atomicAdd(&g_deg[d2.y], 1);
    }
}

// per-block sums of g_deg
__global__ void __launch_bounds__(1024) k_part() {
    __shared__ int wsum[32];
    int t = threadIdx.x, b = blockIdx.x;
    int idx = b * 1024 + t;
    int v = (idx < N_NODES) ? g_deg[idx] : 0;
#pragma unroll
    for (int o = 16; o; o >>= 1) v += __shfl_xor_sync(0xFFFFFFFFu, v, o);
    if ((t & 31) == 0) wsum[t >> 5] = v;
    __syncthreads();
    if (t < 32) {
        int s = wsum[t];
#pragma unroll
        for (int o = 16; o; o >>= 1) s += __shfl_xor_sync(0xFFFFFFFFu, s, o);
        if (t == 0) g_part[b] = s;
    }
}

// node scan -> g_off/g_cur (warp-parallel lookback over g_part)
__global__ void __launch_bounds__(1024) k_off() {
    __shared__ int wsum[32];
    __shared__ int pbase;
    int t = threadIdx.x, b = blockIdx.x;
    int lane = t & 31, wid = t >> 5;

    if (t < 32) {   // parallel lookback: sum g_part[0..b)
        int v = 0;
        if (t < b) v = g_part[t];
        if (t + 32 < b) v += g_part[t + 32];
#pragma unroll
        for (int o = 16; o; o >>= 1) v += __shfl_xor_sync(0xFFFFFFFFu, v, o);
        if (t == 0) pbase = v;
    }
    __syncthreads();

    int idx = b * 1024 + t;
    int v = (idx < N_NODES) ? g_deg[idx] : 0;
    int s = v;
#pragma unroll
    for (int o = 1; o < 32; o <<= 1) {
        int u = __shfl_up_sync(0xFFFFFFFFu, s, o);
        if (lane >= o) s += u;
    }
    if (lane == 31) wsum[wid] = s;
    __syncthreads();
    if (t < 32) {
        int u = wsum[t];
        int ss = u;
#pragma unroll
        for (int o = 1; o < 32; o <<= 1) {
            int q = __shfl_up_sync(0xFFFFFFFFu, ss, o);
            if (t >= o) ss += q;
        }
        wsum[t] = ss - u;   // exclusive warp offset
    }
    __syncthreads();
    int excl = (s - v) + wsum[wid] + pbase;
    if (idx < N_NODES) { g_off[idx] = excl; g_cur[idx] = excl; }
    if (idx == N_NODES) g_off[N_NODES] = excl;
}

// CSR fill: 2 edges/thread + self loops
__global__ void k_fill(const int* __restrict__ ei) {
    int i = blockIdx.x * blockDim.x + threadIdx.x;
    int e2 = i * 2;
    if (e2 < N_EDGES) {
        int2 s2 = *(const int2*)(ei + e2);
        int2 d2 = *(const int2*)(ei + N_EDGES + e2);
        int p0 = atomicAdd(&g_cur[d2.x], 1);
        int p1 = atomicAdd(&g_cur[d2.y], 1);
        g_csr[p0] = s2.x;
        g_csr[p1] = s2.y;
    } else {
        int n = i - N_EDGES / 2;
        if (n >= 0 && n < N_NODES) {
            g_csr[atomicAdd(&g_cur[n], 1)] = n;
        }
    }
}

// warp per dst node: single-pass softmax (global aj-max bound) + fp16 gather
__global__ void __launch_bounds__(256) k_agg(float* __restrict__ out) {
    int node = (blockIdx.x * blockDim.x + threadIdx.x) >> 5;
    int lane = threadIdx.x & 31;
    if (node >= N_NODES) return;
    int beg = g_off[node], end2 = g_off[node + 1];
    float ain = g_ai[node];
    float Mi = lrelu(ain + fdec(g_ajmax_u));

    float4 acc = make_float4(0.f, 0.f, 0.f, 0.f);
    float denom = 0.f;
    int e = beg;
    for (; e + 4 <= end2; e += 4) {
        int s0 = g_csr[e], s1 = g_csr[e + 1], s2 = g_csr[e + 2], s3 = g_csr[e + 3];
        float w0 = __expf(lrelu(ain + g_aj[s0]) - Mi);
        float w1 = __expf(lrelu(ain + g_aj[s1]) - Mi);
        float w2 = __expf(lrelu(ain + g_aj[s2]) - Mi);
        float w3 = __expf(lrelu(ain + g_aj[s3]) - Mi);
        uint2 p0 = g_oxh[s0 * 32 + lane];
        uint2 p1 = g_oxh[s1 * 32 + lane];
        uint2 p2 = g_oxh[s2 * 32 + lane];
        uint2 p3 = g_oxh[s3 * 32 + lane];
        denom += (w0 + w1) + (w2 + w3);
        float2 f01, f23;
        f01 = __half22float2(*reinterpret_cast<const __half2*>(&p0.x));
        f23 = __half22float2(*reinterpret_cast<const __half2*>(&p0.y));
        acc.x += w0 * f01.x; acc.y += w0 * f01.y; acc.z += w0 * f23.x; acc.w += w0 * f23.y;
        f01 = __half22float2(*reinterpret_cast<const __half2*>(&p1.x));
        f23 = __half22float2(*reinterpret_cast<const __half2*>(&p1.y));
        acc.x += w1 * f01.x; acc.y += w1 * f01.y; acc.z += w1 * f23.x; acc.w += w1 * f23.y;
        f01 = __half22float2(*reinterpret_cast<const __half2*>(&p2.x));
        f23 = __half22float2(*reinterpret_cast<const __half2*>(&p2.y));
        acc.x += w2 * f01.x; acc.y += w2 * f01.y; acc.z += w2 * f23.x; acc.w += w2 * f23.y;
        f01 = __half22float2(*reinterpret_cast<const __half2*>(&p3.x));
        f23 = __half22float2(*reinterpret_cast<const __half2*>(&p3.y));
        acc.x += w3 * f01.x; acc.y += w3 * f01.y; acc.z += w3 * f23.x; acc.w += w3 * f23.y;
    }
    for (; e < end2; e++) {
        int s = g_csr[e];
        float w = __expf(lrelu(ain + g_aj[s]) - Mi);
        uint2 p = g_oxh[s * 32 + lane];
        float2 f01 = __half22float2(*reinterpret_cast<const __half2*>(&p.x));
        float2 f23 = __half22float2(*reinterpret_cast<const __half2*>(&p.y));
        denom += w;
        acc.x += w * f01.x; acc.y += w * f01.y; acc.z += w * f23.x; acc.w += w * f23.y;
    }
    float inv = 1.f / (denom + 1e-16f);
    acc.x *= inv; acc.y *= inv; acc.z *= inv; acc.w *= inv;
    ((float4*)out)[node * 32 + lane] = acc;
}

// ---------------- launch (two-stream fork/join) ----------------
extern "C" void kernel_launch(void* const* d_in, const int* in_sizes, int n_in,
                              void* d_out, int out_size) {
    const float* x = nullptr;
    const int* ei = nullptr;
    const int* label = nullptr;
    const float* W = nullptr;
    const float* att = nullptr;
    for (int i = 0; i < n_in; i++) {
        switch (in_sizes[i]) {
            case N_NODES * DD:   x     = (const float*)d_in[i]; break;
            case 2 * N_EDGES:    ei    = (const int*)d_in[i];   break;
            case N_NODES:        label = (const int*)d_in[i];   break;
            case WSZ:            W     = (const float*)d_in[i]; break;
            case 2 * DD:         att   = (const float*)d_in[i]; break;
            default: break;
        }
    }
    float* out = (float*)d_out;

    static cudaStream_t sB = nullptr;
    static cudaEvent_t evFork = nullptr, evJoin = nullptr;
    if (sB == nullptr) {
        cudaStreamCreateWithFlags(&sB, cudaStreamNonBlocking);
        cudaEventCreateWithFlags(&evFork, cudaEventDisableTiming);
        cudaEventCreateWithFlags(&evJoin, cudaEventDisableTiming);
        cudaFuncSetAttribute(k_ox, cudaFuncAttributeMaxDynamicSharedMemorySize, OX_SMEM);
    }

    k_init<<<(WSZ + 255) / 256, 256>>>(W);
    cudaEventRecord(evFork, 0);
    cudaStreamWaitEvent(sB, evFork, 0);

    // stream B: label chain -> k_ox
    k_lab <<<(N_NODES + 255) / 256, 256, 0, sB>>>(label);
    k_scat<<<(N_NODES + 255) / 256, 256, 0, sB>>>(label);
    k_ox  <<<dim3((N_NODES + 127) / 128, NLAB), 256, OX_SMEM, sB>>>(x, att);
    cudaEventRecord(evJoin, sB);

    // stream A (default): degree chain -> CSR
    k_deg <<<(N_EDGES / 2 + 255) / 256, 256>>>(ei);
    k_part<<<NB_SCAN, 1024>>>();
    k_off <<<NB_SCAN, 1024>>>();
    k_fill<<<(N_EDGES / 2 + N_NODES + 255) / 256, 256>>>(ei);

    cudaStreamWaitEvent(0, evJoin, 0);
    k_agg <<<(N_NODES * 32 + 255) / 256, 256>>>(out);
}

// round 17
// speedup vs baseline: 1.0612x; 1.0612x over previous
#include <cuda_runtime.h>
#include <cuda_fp16.h>

#define N_NODES 50000
#define N_EDGES 800000
#define DD 128
#define NEG 0.2f
#define NLAB 8
#define ET (N_EDGES + N_NODES)
#define WSZ (7 * DD * DD)
#define NB_SCAN 49   // ceil(50000/1024)
#define XP 136       // padded smem row stride (halfs): conflict-free

// ---------------- device scratch (no allocs allowed) ----------------
__device__ __align__(16) uint2 g_oxh[N_NODES * 32];  // fp16x4 packed transformed features
__device__ __align__(16) __half g_Wh[WSZ];           // fp16 weights (pre-converted)
__device__ float g_ai[N_NODES];
__device__ float g_aj[N_NODES];
__device__ unsigned g_ajmax_u;                       // ordered-uint encoded max(aj)
__device__ int   g_order[N_NODES];
__device__ int   g_counts[NLAB];
__device__ int   g_base[NLAB + 1];
__device__ int   g_lcur[NLAB];                       // relative label cursors (start 0)
__device__ int   g_deg[N_NODES];
__device__ int   g_off[N_NODES + 1];
__device__ int   g_cur[N_NODES];
__device__ int   g_csr[ET];
__device__ int   g_part[NB_SCAN];

__device__ __forceinline__ unsigned fenc(float f) {
    unsigned u = __float_as_uint(f);
    return (u & 0x80000000u) ? ~u : (u | 0x80000000u);
}
__device__ __forceinline__ float fdec(unsigned u) {
    return (u & 0x80000000u) ? __uint_as_float(u ^ 0x80000000u)
                             : __uint_as_float(~u);
}
__device__ __forceinline__ float lrelu(float a) { return a > 0.f ? a : NEG * a; }

// ---------------- init: counters, degrees, W->fp16 ----------------
__global__ void k_init(const float* __restrict__ W) {
    int i = blockIdx.x * blockDim.x + threadIdx.x;
    if (i < NLAB) { g_counts[i] = 0; g_lcur[i] = 0; }
    if (i == NLAB) g_ajmax_u = 0u;   // encodes -inf
    if (i < N_NODES) g_deg[i] = 1;   // self loop pre-counted
    if (i < WSZ) g_Wh[i] = __float2half_rn(W[i]);
}

// ======== stream B: label chain ========

// label histogram (warp-aggregated)
__global__ void k_lab(const int* __restrict__ label) {
    int i = blockIdx.x * blockDim.x + threadIdx.x;
    if (i >= N_NODES) return;
    int lb = label[i];
    if (lb < 1 || lb > 7) lb = 0;
    unsigned act = __activemask();
    unsigned peers = __match_any_sync(act, lb);
    int leader = __ffs(peers) - 1;
    if ((int)(threadIdx.x & 31) == leader)
        atomicAdd(&g_counts[lb], __popc(peers));
}

// label bases + label-group scatter of node ids into g_order
__global__ void k_scat(const int* __restrict__ label) {
    __shared__ int sbase[NLAB];
    int t = threadIdx.x;
    int i = blockIdx.x * blockDim.x + t;
    if (t == 0) {
        int bb = 0;
        for (int k = 0; k < NLAB; k++) {
            sbase[k] = bb;
            if (blockIdx.x == 0) g_base[k] = bb;
            bb += g_counts[k];
        }
        if (blockIdx.x == 0) g_base[NLAB] = bb;
    }
    __syncthreads();
    if (i >= N_NODES) return;
    int lb = label[i];
    if (lb < 1 || lb > 7) lb = 0;
    int lane = t & 31;
    unsigned act = __activemask();
    unsigned peers = __match_any_sync(act, lb);
    int leader = __ffs(peers) - 1;
    int rank = __popc(peers & ((1u << lane) - 1u));
    int rel = 0;
    if (lane == leader) rel = atomicAdd(&g_lcur[lb], __popc(peers));
    rel = __shfl_sync(act, rel, leader);
    g_order[sbase[lb] + rel + rank] = i;
}

// tensor-core label-grouped GEMM, 64-node tile, 256 threads / 8 warps
// (R15 config = measured best). fp16 W staged as pure int4 copies.
// ox routed through smem, flushed with coalesced STG.64.
__global__ void __launch_bounds__(256) k_ox(const float* __restrict__ x,
                                            const float* __restrict__ att) {
    int k = blockIdx.y;
    int gbase = g_base[k];
    int start = gbase + blockIdx.x * 64;
    int end   = gbase + g_counts[k];
    if (start >= end) return;
    int nEff = min(64, end - start);

    __shared__ __align__(16) __half xs[64 * XP];
    __shared__ __align__(16) __half ws[64 * XP];   // W chunk during mma; ox staging after
    __shared__ float att_s[2 * DD];
    __shared__ int nid[64];
    __shared__ unsigned s_ajmax;
    __shared__ float sSi[64], sSj[64];

    int tid = threadIdx.x;
    int lane = tid & 31, wid = tid >> 5;
    int rowgrp = wid & 3;       // 16-row strip
    int colhalf = wid >> 2;     // 64-col half
    if (tid < 64) nid[tid] = (tid < nEff) ? g_order[start + tid] : g_order[start];
    if (tid < 2 * DD) att_s[tid] = att[tid];
    if (tid == 0) s_ajmax = 0u;
    __syncthreads();

    // stage x rows (fp32 -> fp16, quarter-row per thread)
    {
        int j = tid >> 2, part = tid & 3;
        const float4* xr = (const float4*)x + (size_t)nid[j] * 32 + part * 8;
        __half2* dst = (__half2*)(xs + j * XP + part * 32);
#pragma unroll
        for (int i = 0; i < 8; i++) {
            float4 v = xr[i];
            dst[i * 2 + 0] = __floats2half2_rn(v.x, v.y);
            dst[i * 2 + 1] = __floats2half2_rn(v.z, v.w);
        }
    }
    __syncthreads();   // xs/att_s visible to all warps (incl. k==0 path)

    float d[8][4];
#pragma unroll
    for (int nt = 0; nt < 8; nt++) { d[nt][0] = d[nt][1] = d[nt][2] = d[nt][3] = 0.f; }

    int wrow0 = rowgrp * 16;

    if (k > 0) {
        const int4* Wg = (const int4*)(g_Wh + (size_t)(k - 1) * DD * DD);
        for (int c = 0; c < 2; c++) {
            __syncthreads();
            {
                // stage 64 k-rows x 128 cols fp16: pure int4 copies (16 per row)
                for (int idx = tid; idx < 1024; idx += 256) {
                    int dr = idx >> 4, ii = idx & 15;
                    *(int4*)(ws + dr * XP + ii * 8) = Wg[(c * 64 + dr) * 16 + ii];
                }
            }
            __syncthreads();
#pragma unroll
            for (int kt = 0; kt < 4; kt++) {
                int kb = kt * 16;
                unsigned a0, a1, a2, a3;
                {
                    int r  = (lane & 7) + ((lane >> 3) & 1) * 8;
                    int cc = (lane >> 4) * 8;
                    const __half* ap = xs + (wrow0 + r) * XP + (c * 64 + kb + cc);
                    unsigned sa = (unsigned)__cvta_generic_to_shared(ap);
                    asm volatile("ldmatrix.sync.aligned.m8n8.x4.shared.b16 {%0,%1,%2,%3}, [%4];"
                                 : "=r"(a0), "=r"(a1), "=r"(a2), "=r"(a3) : "r"(sa));
                }
#pragma unroll
                for (int npl = 0; npl < 4; npl++) {
                    int n0 = (colhalf * 4 + npl) * 16;
                    unsigned b0, b1, b2, b3;
                    {
                        int kr = kb + (lane & 7) + ((lane >> 3) & 1) * 8;
                        int nc = n0 + (lane >> 4) * 8;
                        const __half* bp = ws + kr * XP + nc;
                        unsigned sb = (unsigned)__cvta_generic_to_shared(bp);
                        asm volatile("ldmatrix.sync.aligned.m8n8.x4.trans.shared.b16 {%0,%1,%2,%3}, [%4];"
                                     : "=r"(b0), "=r"(b1), "=r"(b2), "=r"(b3) : "r"(sb));
                    }
                    asm volatile("mma.sync.aligned.m16n8k16.row.col.f32.f16.f16.f32 "
                                 "{%0,%1,%2,%3}, {%4,%5,%6,%7}, {%8,%9}, {%0,%1,%2,%3};"
                                 : "+f"(d[npl*2][0]), "+f"(d[npl*2][1]), "+f"(d[npl*2][2]), "+f"(d[npl*2][3])
                                 : "r"(a0), "r"(a1), "r"(a2), "r"(a3), "r"(b0), "r"(b1));
                    asm volatile("mma.sync.aligned.m16n8k16.row.col.f32.f16.f16.f32 "
                                 "{%0,%1,%2,%3}, {%4,%5,%6,%7}, {%8,%9}, {%0,%1,%2,%3};"
                                 : "+f"(d[npl*2+1][0]), "+f"(d[npl*2+1][1]), "+f"(d[npl*2+1][2]), "+f"(d[npl*2+1][3])
                                 : "r"(a0), "r"(a1), "r"(a2), "r"(a3), "r"(b2), "r"(b3));
                }
            }
        }
    }
    __syncthreads();   // all warps done reading ws -> reuse as ox staging

    __half* os = ws;   // 64 x XP ox staging

    // fragment-native dots + smem ox store (conflict-free: bank = (4r+q)%32)
    int q  = lane & 3;
    int r0 = wrow0 + (lane >> 2);
    int r1 = r0 + 8;
    int j0ok = (r0 < nEff), j1ok = (r1 < nEff);
    int node0 = nid[r0], node1 = nid[r1];

    float si0 = 0.f, sj0 = 0.f, si1 = 0.f, sj1 = 0.f;
#pragma unroll
    for (int ntl = 0; ntl < 8; ntl++) {
        int cc = colhalf * 64 + ntl * 8 + 2 * q;
        float av0 = att_s[cc], av1 = att_s[cc + 1];
        float bv0 = att_s[DD + cc], bv1 = att_s[DD + cc + 1];
        float2 x0 = __half22float2(*(const __half2*)(xs + r0 * XP + cc));
        float2 x1 = __half22float2(*(const __half2*)(xs + r1 * XP + cc));
        float v00 = x0.x + d[ntl][0], v01 = x0.y + d[ntl][1];
        float v10 = x1.x + d[ntl][2], v11 = x1.y + d[ntl][3];
        si0 += v00 * av0 + v01 * av1;
        sj0 += v00 * bv0 + v01 * bv1;
        si1 += v10 * av0 + v11 * av1;
        sj1 += v10 * bv0 + v11 * bv1;
        *(__half2*)(os + r0 * XP + cc) = __floats2half2_rn(v00, v01);
        *(__half2*)(os + r1 * XP + cc) = __floats2half2_rn(v10, v11);
    }
#pragma unroll
    for (int o = 1; o <= 2; o <<= 1) {
        si0 += __shfl_xor_sync(0xFFFFFFFFu, si0, o);
        sj0 += __shfl_xor_sync(0xFFFFFFFFu, sj0, o);
        si1 += __shfl_xor_sync(0xFFFFFFFFu, si1, o);
        sj1 += __shfl_xor_sync(0xFFFFFFFFu, sj1, o);
    }
    // combine the two column halves via smem
    if (colhalf == 0 && q == 0) {
        sSi[r0] = si0; sSj[r0] = sj0;
        sSi[r1] = si1; sSj[r1] = sj1;
    }
    __syncthreads();   // covers sSi/sSj AND os completion
    if (colhalf == 1 && q == 0) {
        float Si0 = si0 + sSi[r0], Sj0 = sj0 + sSj[r0];
        float Si1 = si1 + sSi[r1], Sj1 = sj1 + sSj[r1];
        unsigned mx = 0u;
        if (j0ok) { g_ai[node0] = Si0; g_aj[node0] = Sj0; mx = fenc(Sj0); }
        if (j1ok) { g_ai[node1] = Si1; g_aj[node1] = Sj1; unsigned m1 = fenc(Sj1); if (m1 > mx) mx = m1; }
        if (mx) atomicMax(&s_ajmax, mx);
    }

    // coalesced ox flush: warp per row, STG.64 -> one contiguous 256B row
    {
        int jb = wid * 8;
#pragma unroll
        for (int rr = 0; rr < 8; rr++) {
            int j = jb + rr;
            if (j < nEff) {
                uint2 v = *(const uint2*)(os + j * XP + lane * 4);
                g_oxh[(size_t)nid[j] * 32 + lane] = v;
            }
        }
    }
    __syncthreads();
    if (tid == 0 && s_ajmax) atomicMax(&g_ajmax_u, s_ajmax);
}

// ======== stream A (default): degree chain ========

// in-degree count, 2 edges/thread
__global__ void k_deg(const int* __restrict__ ei) {
    int i = blockIdx.x * blockDim.x + threadIdx.x;
    int e2 = i * 2;
    if (e2 < N_EDGES) {
        int2 d2 = *(const int2*)(ei + N_EDGES + e2);
        atomicAdd(&g_deg[d2.x], 1);
        atomicAdd(&g_deg[d2.y], 1);
    }
}

// per-block sums of g_deg
__global__ void __launch_bounds__(1024) k_part() {
    __shared__ int wsum[32];
    int t = threadIdx.x, b = blockIdx.x;
    int idx = b * 1024 + t;
    int v = (idx < N_NODES) ? g_deg[idx] : 0;
#pragma unroll
    for (int o = 16; o; o >>= 1) v += __shfl_xor_sync(0xFFFFFFFFu, v, o);
    if ((t & 31) == 0) wsum[t >> 5] = v;
    __syncthreads();
    if (t < 32) {
        int s = wsum[t];
#pragma unroll
        for (int o = 16; o; o >>= 1) s += __shfl_xor_sync(0xFFFFFFFFu, s, o);
        if (t == 0) g_part[b] = s;
    }
}

// node scan -> g_off/g_cur (warp-parallel lookback over g_part)
__global__ void __launch_bounds__(1024) k_off() {
    __shared__ int wsum[32];
    __shared__ int pbase;
    int t = threadIdx.x, b = blockIdx.x;
    int lane = t & 31, wid = t >> 5;

    if (t < 32) {   // parallel lookback: sum g_part[0..b)
        int v = 0;
        if (t < b) v = g_part[t];
        if (t + 32 < b) v += g_part[t + 32];
#pragma unroll
        for (int o = 16; o; o >>= 1) v += __shfl_xor_sync(0xFFFFFFFFu, v, o);
        if (t == 0) pbase = v;
    }
    __syncthreads();

    int idx = b * 1024 + t;
    int v = (idx < N_NODES) ? g_deg[idx] : 0;
    int s = v;
#pragma unroll
    for (int o = 1; o < 32; o <<= 1) {
        int u = __shfl_up_sync(0xFFFFFFFFu, s, o);
        if (lane >= o) s += u;
    }
    if (lane == 31) wsum[wid] = s;
    __syncthreads();
    if (t < 32) {
        int u = wsum[t];
        int ss = u;
#pragma unroll
        for (int o = 1; o < 32; o <<= 1) {
            int q = __shfl_up_sync(0xFFFFFFFFu, ss, o);
            if (t >= o) ss += q;
        }
        wsum[t] = ss - u;   // exclusive warp offset
    }
    __syncthreads();
    int excl = (s - v) + wsum[wid] + pbase;
    if (idx < N_NODES) { g_off[idx] = excl; g_cur[idx] = excl; }
    if (idx == N_NODES) g_off[N_NODES] = excl;
}

// CSR fill: 2 edges/thread + self loops
__global__ void k_fill(const int* __restrict__ ei) {
    int i = blockIdx.x * blockDim.x + threadIdx.x;
    int e2 = i * 2;
    if (e2 < N_EDGES) {
        int2 s2 = *(const int2*)(ei + e2);
        int2 d2 = *(const int2*)(ei + N_EDGES + e2);
        int p0 = atomicAdd(&g_cur[d2.x], 1);
        int p1 = atomicAdd(&g_cur[d2.y], 1);
        g_csr[p0] = s2.x;
        g_csr[p1] = s2.y;
    } else {
        int n = i - N_EDGES / 2;
        if (n >= 0 && n < N_NODES) {
            g_csr[atomicAdd(&g_cur[n], 1)] = n;
        }
    }
}

// warp per dst node: single-pass softmax (global aj-max bound) + fp16 gather
__global__ void __launch_bounds__(256) k_agg(float* __restrict__ out) {
    int node = (blockIdx.x * blockDim.x + threadIdx.x) >> 5;
    int lane = threadIdx.x & 31;
    if (node >= N_NODES) return;
    int beg = g_off[node], end2 = g_off[node + 1];
    float ain = g_ai[node];
    float Mi = lrelu(ain + fdec(g_ajmax_u));

    float4 acc = make_float4(0.f, 0.f, 0.f, 0.f);
    float denom = 0.f;
    int e = beg;
    for (; e + 4 <= end2; e += 4) {
        int s0 = g_csr[e], s1 = g_csr[e + 1], s2 = g_csr[e + 2], s3 = g_csr[e + 3];
        float w0 = __expf(lrelu(ain + g_aj[s0]) - Mi);
        float w1 = __expf(lrelu(ain + g_aj[s1]) - Mi);
        float w2 = __expf(lrelu(ain + g_aj[s2]) - Mi);
        float w3 = __expf(lrelu(ain + g_aj[s3]) - Mi);
        uint2 p0 = g_oxh[s0 * 32 + lane];
        uint2 p1 = g_oxh[s1 * 32 + lane];
        uint2 p2 = g_oxh[s2 * 32 + lane];
        uint2 p3 = g_oxh[s3 * 32 + lane];
        denom += (w0 + w1) + (w2 + w3);
        float2 f01, f23;
        f01 = __half22float2(*reinterpret_cast<const __half2*>(&p0.x));
        f23 = __half22float2(*reinterpret_cast<const __half2*>(&p0.y));
        acc.x += w0 * f01.x; acc.y += w0 * f01.y; acc.z += w0 * f23.x; acc.w += w0 * f23.y;
        f01 = __half22float2(*reinterpret_cast<const __half2*>(&p1.x));
        f23 = __half22float2(*reinterpret_cast<const __half2*>(&p1.y));
        acc.x += w1 * f01.x; acc.y += w1 * f01.y; acc.z += w1 * f23.x; acc.w += w1 * f23.y;
        f01 = __half22float2(*reinterpret_cast<const __half2*>(&p2.x));
        f23 = __half22float2(*reinterpret_cast<const __half2*>(&p2.y));
        acc.x += w2 * f01.x; acc.y += w2 * f01.y; acc.z += w2 * f23.x; acc.w += w2 * f23.y;
        f01 = __half22float2(*reinterpret_cast<const __half2*>(&p3.x));
        f23 = __half22float2(*reinterpret_cast<const __half2*>(&p3.y));
        acc.x += w3 * f01.x; acc.y += w3 * f01.y; acc.z += w3 * f23.x; acc.w += w3 * f23.y;
    }
    for (; e < end2; e++) {
        int s = g_csr[e];
        float w = __expf(lrelu(ain + g_aj[s]) - Mi);
        uint2 p = g_oxh[s * 32 + lane];
        float2 f01 = __half22float2(*reinterpret_cast<const __half2*>(&p.x));
        float2 f23 = __half22float2(*reinterpret_cast<const __half2*>(&p.y));
        denom += w;
        acc.x += w * f01.x; acc.y += w * f01.y; acc.z += w * f23.x; acc.w += w * f23.y;
    }
    float inv = 1.f / (denom + 1e-16f);
    acc.x *= inv; acc.y *= inv; acc.z *= inv; acc.w *= inv;
    ((float4*)out)[node * 32 + lane] = acc;
}

// ---------------- launch (two-stream fork/join) ----------------
extern "C" void kernel_launch(void* const* d_in, const int* in_sizes, int n_in,
                              void* d_out, int out_size) {
    const float* x = nullptr;
    const int* ei = nullptr;
    const int* label = nullptr;
    const float* W = nullptr;
    const float* att = nullptr;
    for (int i = 0; i < n_in; i++) {
        switch (in_sizes[i]) {
            case N_NODES * DD:   x     = (const float*)d_in[i]; break;
            case 2 * N_EDGES:    ei    = (const int*)d_in[i];   break;
            case N_NODES:        label = (const int*)d_in[i];   break;
            case WSZ:            W     = (const float*)d_in[i]; break;
            case 2 * DD:         att   = (const float*)d_in[i]; break;
            default: break;
        }
    }
    float* out = (float*)d_out;

    static cudaStream_t sB = nullptr;
    static cudaEvent_t evFork = nullptr, evJoin = nullptr;
    if (sB == nullptr) {
        cudaStreamCreateWithFlags(&sB, cudaStreamNonBlocking);
        cudaEventCreateWithFlags(&evFork, cudaEventDisableTiming);
        cudaEventCreateWithFlags(&evJoin, cudaEventDisableTiming);
    }

    k_init<<<(WSZ + 255) / 256, 256>>>(W);
    cudaEventRecord(evFork, 0);
    cudaStreamWaitEvent(sB, evFork, 0);

    // stream B: label chain -> k_ox
    k_lab <<<(N_NODES + 255) / 256, 256, 0, sB>>>(label);
    k_scat<<<(N_NODES + 255) / 256, 256, 0, sB>>>(label);
    k_ox  <<<dim3((N_NODES + 63) / 64, NLAB), 256, 0, sB>>>(x, att);
    cudaEventRecord(evJoin, sB);

    // stream A (default): degree chain -> CSR
    k_deg <<<(N_EDGES / 2 + 255) / 256, 256>>>(ei);
    k_part<<<NB_SCAN, 1024>>>();
    k_off <<<NB_SCAN, 1024>>>();
    k_fill<<<(N_EDGES / 2 + N_NODES + 255) / 256, 256>>>(ei);

    cudaStreamWaitEvent(0, evJoin, 0);
    k_agg <<<(N_NODES * 32 + 255) / 256, 256>>>(out);
}